// round 2
// baseline (speedup 1.0000x reference)
#include <cuda_runtime.h>
#include <cuda_bf16.h>
#include <math_constants.h>

#define N_NODES 50000
#define N_EDGES 800000
#define IN_CH   64
#define HEADS   4
#define OUT_CH  64
#define HC      (HEADS * OUT_CH)   // 256
#define NEG_SLOPE 0.2f

// ---------------- device scratch (static, no allocation) ----------------
__device__ __align__(16) float g_xt[(size_t)N_NODES * HC];   // [N, 256]
__device__ __align__(16) float g_asrc[N_NODES * HEADS];      // [N, 4]
__device__ __align__(16) float g_adst[N_NODES * HEADS];      // [N, 4]
__device__ int   g_count[N_NODES];
__device__ int   g_offs[N_NODES];
__device__ int   g_cursor[N_NODES];
__device__ int   g_esrc[N_EDGES];

// ---------------- K1: xt = x @ W  (register-blocked 4x4) ----------------
__global__ void gemm_kernel(const float* __restrict__ x,
                            const float* __restrict__ W) {
    __shared__ float xs[16][64];
    const int tid  = threadIdx.x;
    const int nblk = blockIdx.x * 16;

    for (int i = tid; i < 16 * 64; i += 256) {
        int n = i >> 6, k = i & 63;
        int node = nblk + n;
        xs[n][k] = (node < N_NODES) ? x[(size_t)node * IN_CH + k] : 0.0f;
    }
    __syncthreads();

    const int tx = tid & 63;
    const int ty = tid >> 6;
    const int o0 = tx * 4;
    const int n0 = ty * 4;

    float acc[4][4];
#pragma unroll
    for (int a = 0; a < 4; a++)
#pragma unroll
        for (int b = 0; b < 4; b++) acc[a][b] = 0.0f;

#pragma unroll 8
    for (int k = 0; k < 64; k++) {
        float4 w4 = __ldg((const float4*)(W + (size_t)k * HC + o0));
        float xv0 = xs[n0 + 0][k];
        float xv1 = xs[n0 + 1][k];
        float xv2 = xs[n0 + 2][k];
        float xv3 = xs[n0 + 3][k];
        acc[0][0] += xv0 * w4.x; acc[0][1] += xv0 * w4.y; acc[0][2] += xv0 * w4.z; acc[0][3] += xv0 * w4.w;
        acc[1][0] += xv1 * w4.x; acc[1][1] += xv1 * w4.y; acc[1][2] += xv1 * w4.z; acc[1][3] += xv1 * w4.w;
        acc[2][0] += xv2 * w4.x; acc[2][1] += xv2 * w4.y; acc[2][2] += xv2 * w4.z; acc[2][3] += xv2 * w4.w;
        acc[3][0] += xv3 * w4.x; acc[3][1] += xv3 * w4.y; acc[3][2] += xv3 * w4.z; acc[3][3] += xv3 * w4.w;
    }

#pragma unroll
    for (int nn = 0; nn < 4; nn++) {
        int node = nblk + n0 + nn;
        if (node < N_NODES) {
            float4 v = make_float4(acc[nn][0], acc[nn][1], acc[nn][2], acc[nn][3]);
            *(float4*)(g_xt + (size_t)node * HC + o0) = v;
        }
    }
}

// ---------------- K2: a_src / a_dst per node (one warp/node) ----------------
__global__ void attn_kernel(const float* __restrict__ att_src,
                            const float* __restrict__ att_dst) {
    int gw   = (blockIdx.x * blockDim.x + threadIdx.x) >> 5;
    int lane = threadIdx.x & 31;
    if (gw >= N_NODES) return;

    const float* row = g_xt + (size_t)gw * HC;
    float ps[4] = {0, 0, 0, 0};
    float pd[4] = {0, 0, 0, 0};
#pragma unroll
    for (int k = 0; k < 8; k++) {
        int g = lane + 32 * k;
        float v = row[g];
        ps[k >> 1] += v * __ldg(att_src + g);
        pd[k >> 1] += v * __ldg(att_dst + g);
    }
#pragma unroll
    for (int off = 16; off > 0; off >>= 1) {
#pragma unroll
        for (int h = 0; h < 4; h++) {
            ps[h] += __shfl_down_sync(0xFFFFFFFFu, ps[h], off);
            pd[h] += __shfl_down_sync(0xFFFFFFFFu, pd[h], off);
        }
    }
    if (lane == 0) {
        *(float4*)(g_asrc + gw * 4) = make_float4(ps[0], ps[1], ps[2], ps[3]);
        *(float4*)(g_adst + gw * 4) = make_float4(pd[0], pd[1], pd[2], pd[3]);
    }
}

// ---------------- K3: CSR build ----------------
__global__ void zero_count_kernel() {
    int i = blockIdx.x * blockDim.x + threadIdx.x;
    if (i < N_NODES) g_count[i] = 0;
}

// edge_index is int32 [2, E] (JAX x64 disabled -> int64 request silently int32)
__global__ void count_kernel(const int* __restrict__ ei) {
    int i = blockIdx.x * blockDim.x + threadIdx.x;
    if (i < N_EDGES) {
        int dst = ei[N_EDGES + i];
        if ((unsigned)dst < (unsigned)N_NODES)
            atomicAdd(&g_count[dst], 1);
    }
}

__global__ void scan_kernel() {
    __shared__ int partial[1024];
    const int t = threadIdx.x;
    const int chunk = (N_NODES + 1023) / 1024;   // 49
    int start = t * chunk;
    int end   = min(start + chunk, N_NODES);

    int sum = 0;
    for (int i = start; i < end; i++) sum += g_count[i];
    partial[t] = sum;
    __syncthreads();
    for (int off = 1; off < 1024; off <<= 1) {
        int v = (t >= off) ? partial[t - off] : 0;
        __syncthreads();
        partial[t] += v;
        __syncthreads();
    }
    int run = (t == 0) ? 0 : partial[t - 1];
    for (int i = start; i < end; i++) {
        g_offs[i] = run;
        g_cursor[i] = run;
        run += g_count[i];
    }
}

__global__ void scatter_kernel(const int* __restrict__ ei) {
    int i = blockIdx.x * blockDim.x + threadIdx.x;
    if (i < N_EDGES) {
        int src = ei[i];
        int dst = ei[N_EDGES + i];
        if ((unsigned)dst < (unsigned)N_NODES && (unsigned)src < (unsigned)N_NODES) {
            int pos = atomicAdd(&g_cursor[dst], 1);
            if ((unsigned)pos < (unsigned)N_EDGES) g_esrc[pos] = src;
        }
    }
}

// ---------------- K4: streaming-softmax aggregation + head-mean + relu + fc ----------------
__global__ void agg_kernel(const float* __restrict__ bias,
                           const float* __restrict__ fc_w,
                           const float* __restrict__ fc_b,
                           float* __restrict__ out) {
    int i    = (blockIdx.x * blockDim.x + threadIdx.x) >> 5;
    int lane = threadIdx.x & 31;
    if (i >= N_NODES) return;

    float4 adv = *(const float4*)(g_adst + i * 4);
    float ad[4] = {adv.x, adv.y, adv.z, adv.w};

    float m[4]  = {-CUDART_INF_F, -CUDART_INF_F, -CUDART_INF_F, -CUDART_INF_F};
    float s[4]  = {0, 0, 0, 0};
    float acc[8] = {0, 0, 0, 0, 0, 0, 0, 0};

    const int start = g_offs[i];
    const int deg   = g_count[i];

    for (int e = 0; e <= deg; e++) {           // last iteration = self-loop
        int j = (e < deg) ? g_esrc[start + e] : i;
        float4 asv = *(const float4*)(g_asrc + j * 4);
        float ee[4] = {asv.x + ad[0], asv.y + ad[1], asv.z + ad[2], asv.w + ad[3]};
        float w[4];
#pragma unroll
        for (int h = 0; h < 4; h++) {
            float eh = ee[h];
            eh = (eh > 0.0f) ? eh : NEG_SLOPE * eh;
            if (eh > m[h]) {
                float sc = __expf(m[h] - eh);   // exp(-inf)=0 on first edge
                s[h] *= sc;
                acc[2 * h]     *= sc;
                acc[2 * h + 1] *= sc;
                m[h] = eh;
            }
            w[h] = __expf(eh - m[h]);
            s[h] += w[h];
        }
        const float* row = g_xt + (size_t)j * HC;
#pragma unroll
        for (int k = 0; k < 8; k++)
            acc[k] += w[k >> 1] * __ldg(row + lane + 32 * k);
    }

    float inv[4];
#pragma unroll
    for (int h = 0; h < 4; h++) inv[h] = 0.25f / s[h];

    float v1 = acc[0] * inv[0] + acc[2] * inv[1] + acc[4] * inv[2] + acc[6] * inv[3];
    float v2 = acc[1] * inv[0] + acc[3] * inv[1] + acc[5] * inv[2] + acc[7] * inv[3];

    float h1 = fmaxf(v1 + __ldg(bias + lane), 0.0f);
    float h2 = fmaxf(v2 + __ldg(bias + lane + 32), 0.0f);
    float p  = h1 * __ldg(fc_w + lane) + h2 * __ldg(fc_w + lane + 32);

#pragma unroll
    for (int off = 16; off > 0; off >>= 1)
        p += __shfl_down_sync(0xFFFFFFFFu, p, off);

    if (lane == 0) out[i] = p + __ldg(fc_b);
}

// ---------------- launch ----------------
extern "C" void kernel_launch(void* const* d_in, const int* in_sizes, int n_in,
                              void* d_out, int out_size) {
    const float* x        = (const float*)d_in[0];
    const int*   ei       = (const int*)d_in[1];     // int32 [2, E]
    const float* W        = (const float*)d_in[2];
    const float* att_src  = (const float*)d_in[3];
    const float* att_dst  = (const float*)d_in[4];
    const float* bias     = (const float*)d_in[5];
    const float* fc_w     = (const float*)d_in[6];
    const float* fc_b     = (const float*)d_in[7];
    float*       out      = (float*)d_out;

    (void)in_sizes; (void)n_in; (void)out_size;

    gemm_kernel<<<(N_NODES + 15) / 16, 256>>>(x, W);
    attn_kernel<<<(N_NODES * 32 + 255) / 256, 256>>>(att_src, att_dst);
    zero_count_kernel<<<(N_NODES + 255) / 256, 256>>>();
    count_kernel<<<(N_EDGES + 255) / 256, 256>>>(ei);
    scan_kernel<<<1, 1024>>>();
    scatter_kernel<<<(N_EDGES + 255) / 256, 256>>>(ei);
    agg_kernel<<<(N_NODES * 32 + 255) / 256, 256>>>(bias, fc_w, fc_b, out);
}

// round 4
// speedup vs baseline: 2.0170x; 2.0170x over previous
#include <cuda_runtime.h>
#include <cuda_fp16.h>
#include <math_constants.h>

#define N_NODES 50000
#define N_EDGES 800000
#define IN_CH   64
#define HEADS   4
#define OUT_CH  64
#define HC      (HEADS * OUT_CH)   // 256
#define NEG_SLOPE 0.2f
#define NBLK_NODES 196             // ceil(50000/256)

// ---------------- device scratch ----------------
__device__ __align__(16) __half2 g_xth[(size_t)N_NODES * (HC / 2)]; // [N,128] fp16x2 pairs
__device__ __align__(16) float g_asrc[N_NODES * HEADS];
__device__ __align__(16) float g_adst[N_NODES * HEADS];
__device__ __align__(16) float4 g_w[N_EDGES];      // per-edge softmax numerators (dst-sorted)
__device__ int   g_count[N_NODES];
__device__ int   g_offs[N_NODES];
__device__ int   g_cursor[N_NODES];
__device__ int   g_esrc[N_EDGES];
__device__ int   g_bsum[256];
__device__ int   g_boff[256];

__device__ __forceinline__ float leaky(float v) {
    return (v > 0.0f) ? v : NEG_SLOPE * v;
}

// ---------------- K1: xt = x @ W, fused fp16 pack + attention logits ----------------
// 256 threads; 16 nodes x 256 outs; thread (ty,tx) -> nodes n0..n0+3, outs o0..o0+3.
__global__ void gemm_kernel(const float* __restrict__ x,
                            const float* __restrict__ W,
                            const float* __restrict__ att_src,
                            const float* __restrict__ att_dst) {
    __shared__ float xs[16][64];
    const int tid  = threadIdx.x;
    const int nblk = blockIdx.x * 16;

    for (int i = tid; i < 16 * 64; i += 256) {
        int n = i >> 6, k = i & 63;
        int node = nblk + n;
        xs[n][k] = (node < N_NODES) ? x[(size_t)node * IN_CH + k] : 0.0f;
    }
    __syncthreads();

    const int tx = tid & 63;
    const int ty = tid >> 6;
    const int o0 = tx * 4;
    const int n0 = ty * 4;
    const int h  = o0 >> 6;          // head of this thread's 4 outs

    float acc[4][4];
#pragma unroll
    for (int a = 0; a < 4; a++)
#pragma unroll
        for (int b = 0; b < 4; b++) acc[a][b] = 0.0f;

#pragma unroll 8
    for (int k = 0; k < 64; k++) {
        float4 w4 = __ldg((const float4*)(W + (size_t)k * HC + o0));
        float xv0 = xs[n0 + 0][k];
        float xv1 = xs[n0 + 1][k];
        float xv2 = xs[n0 + 2][k];
        float xv3 = xs[n0 + 3][k];
        acc[0][0] += xv0 * w4.x; acc[0][1] += xv0 * w4.y; acc[0][2] += xv0 * w4.z; acc[0][3] += xv0 * w4.w;
        acc[1][0] += xv1 * w4.x; acc[1][1] += xv1 * w4.y; acc[1][2] += xv1 * w4.z; acc[1][3] += xv1 * w4.w;
        acc[2][0] += xv2 * w4.x; acc[2][1] += xv2 * w4.y; acc[2][2] += xv2 * w4.z; acc[2][3] += xv2 * w4.w;
        acc[3][0] += xv3 * w4.x; acc[3][1] += xv3 * w4.y; acc[3][2] += xv3 * w4.z; acc[3][3] += xv3 * w4.w;
    }

    // fp16-pack store
#pragma unroll
    for (int nn = 0; nn < 4; nn++) {
        int node = nblk + n0 + nn;
        if (node < N_NODES) {
            __half2 p0 = __floats2half2_rn(acc[nn][0], acc[nn][1]);
            __half2 p1 = __floats2half2_rn(acc[nn][2], acc[nn][3]);
            uint2 v = make_uint2(*(unsigned*)&p0, *(unsigned*)&p1);
            *(uint2*)(g_xth + (size_t)node * (HC / 2) + (o0 >> 1)) = v;
        }
    }

    // fused attention logits: reduce over 16 lanes covering one head
    float a0 = __ldg(att_src + o0),     a1 = __ldg(att_src + o0 + 1);
    float a2 = __ldg(att_src + o0 + 2), a3 = __ldg(att_src + o0 + 3);
    float d0 = __ldg(att_dst + o0),     d1 = __ldg(att_dst + o0 + 1);
    float d2 = __ldg(att_dst + o0 + 2), d3 = __ldg(att_dst + o0 + 3);

    float ps[4], pd[4];
#pragma unroll
    for (int nn = 0; nn < 4; nn++) {
        ps[nn] = acc[nn][0] * a0 + acc[nn][1] * a1 + acc[nn][2] * a2 + acc[nn][3] * a3;
        pd[nn] = acc[nn][0] * d0 + acc[nn][1] * d1 + acc[nn][2] * d2 + acc[nn][3] * d3;
    }
#pragma unroll
    for (int off = 8; off > 0; off >>= 1) {
#pragma unroll
        for (int nn = 0; nn < 4; nn++) {
            ps[nn] += __shfl_down_sync(0xFFFFFFFFu, ps[nn], off, 16);
            pd[nn] += __shfl_down_sync(0xFFFFFFFFu, pd[nn], off, 16);
        }
    }
    if ((tx & 15) == 0) {
#pragma unroll
        for (int nn = 0; nn < 4; nn++) {
            int node = nblk + n0 + nn;
            if (node < N_NODES) {
                g_asrc[node * 4 + h] = ps[nn];
                g_adst[node * 4 + h] = pd[nn];
            }
        }
    }
}

// ---------------- K2: CSR build ----------------
__global__ void zero_count_kernel() {
    int i = blockIdx.x * blockDim.x + threadIdx.x;
    if (i < N_NODES) g_count[i] = 0;
}

__global__ void count_kernel(const int* __restrict__ ei) {
    int i = blockIdx.x * blockDim.x + threadIdx.x;
    if (i < N_EDGES) {
        int dst = ei[N_EDGES + i];
        if ((unsigned)dst < (unsigned)N_NODES)
            atomicAdd(&g_count[dst], 1);
    }
}

// phase A: per-block sums of counts
__global__ void scanA_kernel() {
    __shared__ int wsum[8];
    int i = blockIdx.x * 256 + threadIdx.x;
    int c = (i < N_NODES) ? g_count[i] : 0;
    int v = c;
#pragma unroll
    for (int off = 16; off > 0; off >>= 1)
        v += __shfl_down_sync(0xFFFFFFFFu, v, off);
    if ((threadIdx.x & 31) == 0) wsum[threadIdx.x >> 5] = v;
    __syncthreads();
    if (threadIdx.x == 0) {
        int s = 0;
#pragma unroll
        for (int w = 0; w < 8; w++) s += wsum[w];
        g_bsum[blockIdx.x] = s;
    }
}

// phase B: exclusive scan of 196 block sums (one block, 256 threads)
__global__ void scanB_kernel() {
    __shared__ int sm[256];
    int t = threadIdx.x;
    int v = (t < NBLK_NODES) ? g_bsum[t] : 0;
    sm[t] = v;
    __syncthreads();
    for (int off = 1; off < 256; off <<= 1) {
        int u = (t >= off) ? sm[t - off] : 0;
        __syncthreads();
        sm[t] += u;
        __syncthreads();
    }
    if (t < NBLK_NODES) g_boff[t] = sm[t] - v;   // exclusive
}

// phase C: block-local exclusive scan + base offset
__global__ void scanC_kernel() {
    __shared__ int sm[256];
    int t = threadIdx.x;
    int i = blockIdx.x * 256 + t;
    int c = (i < N_NODES) ? g_count[i] : 0;
    sm[t] = c;
    __syncthreads();
    for (int off = 1; off < 256; off <<= 1) {
        int u = (t >= off) ? sm[t - off] : 0;
        __syncthreads();
        sm[t] += u;
        __syncthreads();
    }
    if (i < N_NODES) {
        int off = g_boff[blockIdx.x] + sm[t] - c;
        g_offs[i] = off;
        g_cursor[i] = off;
    }
}

// ---------------- K3: scatter + edge-weight precompute ----------------
// softmax is shift-invariant; logits are O(10) so raw exp is safe in fp32.
__global__ void scatter_kernel(const int* __restrict__ ei) {
    int i = blockIdx.x * blockDim.x + threadIdx.x;
    if (i >= N_EDGES) return;
    int src = ei[i];
    int dst = ei[N_EDGES + i];
    if ((unsigned)dst >= (unsigned)N_NODES || (unsigned)src >= (unsigned)N_NODES) return;
    int pos = atomicAdd(&g_cursor[dst], 1);
    g_esrc[pos] = src;
    float4 as = *(const float4*)(g_asrc + src * 4);
    float4 ad = *(const float4*)(g_adst + dst * 4);
    float4 w;
    w.x = __expf(leaky(as.x + ad.x));
    w.y = __expf(leaky(as.y + ad.y));
    w.z = __expf(leaky(as.z + ad.z));
    w.w = __expf(leaky(as.w + ad.w));
    g_w[pos] = w;
}

// ---------------- K4: gather-aggregate + head-mean + relu + fc ----------------
// one warp per dst node; lane covers channel pairs (2*lane, 2*lane+1) of each head.
__global__ void agg_kernel(const float* __restrict__ bias,
                           const float* __restrict__ fc_w,
                           const float* __restrict__ fc_b,
                           float* __restrict__ out) {
    int i    = (blockIdx.x * blockDim.x + threadIdx.x) >> 5;
    int lane = threadIdx.x & 31;
    if (i >= N_NODES) return;

    const int start = g_offs[i];
    const int deg   = g_count[i];

    // self-loop weight
    float4 as = *(const float4*)(g_asrc + i * 4);
    float4 ad = *(const float4*)(g_adst + i * 4);
    float4 selfw;
    selfw.x = __expf(leaky(as.x + ad.x));
    selfw.y = __expf(leaky(as.y + ad.y));
    selfw.z = __expf(leaky(as.z + ad.z));
    selfw.w = __expf(leaky(as.w + ad.w));

    float2 acc[4] = {{0,0},{0,0},{0,0},{0,0}};
    float  s[4]   = {0,0,0,0};

    // software pipeline: prefetch next (j, w4)
    int jn; float4 wn;
    if (deg > 0) { jn = __ldg(g_esrc + start); wn = g_w[start]; }
    else         { jn = i; wn = selfw; }

    for (int e = 0; e <= deg; e++) {
        int j = jn; float4 w = wn;
        int en = e + 1;
        if (en < deg)       { jn = __ldg(g_esrc + start + en); wn = g_w[start + en]; }
        else if (en == deg) { jn = i; wn = selfw; }

        s[0] += w.x; s[1] += w.y; s[2] += w.z; s[3] += w.w;
        const __half2* row = g_xth + (size_t)j * (HC / 2);
        float wh[4] = {w.x, w.y, w.z, w.w};
#pragma unroll
        for (int k = 0; k < 4; k++) {
            __half2 hv = __ldg(row + lane + 32 * k);
            float2 f = __half22float2(hv);
            acc[k].x += wh[k] * f.x;
            acc[k].y += wh[k] * f.y;
        }
    }

    // mean over heads (channel-within-head pair index == lane for every head)
    float vlo = 0.0f, vhi = 0.0f;
#pragma unroll
    for (int k = 0; k < 4; k++) {
        float inv = 0.25f / s[k];
        vlo += acc[k].x * inv;
        vhi += acc[k].y * inv;
    }

    float2 b2 = __ldg((const float2*)(bias + 2 * lane));
    float2 f2 = __ldg((const float2*)(fc_w + 2 * lane));
    float h1 = fmaxf(vlo + b2.x, 0.0f);
    float h2 = fmaxf(vhi + b2.y, 0.0f);
    float p  = h1 * f2.x + h2 * f2.y;

#pragma unroll
    for (int off = 16; off > 0; off >>= 1)
        p += __shfl_down_sync(0xFFFFFFFFu, p, off);

    if (lane == 0) out[i] = p + __ldg(fc_b);
}

// ---------------- launch ----------------
extern "C" void kernel_launch(void* const* d_in, const int* in_sizes, int n_in,
                              void* d_out, int out_size) {
    const float* x        = (const float*)d_in[0];
    const int*   ei       = (const int*)d_in[1];     // int32 [2, E]
    const float* W        = (const float*)d_in[2];
    const float* att_src  = (const float*)d_in[3];
    const float* att_dst  = (const float*)d_in[4];
    const float* bias     = (const float*)d_in[5];
    const float* fc_w     = (const float*)d_in[6];
    const float* fc_b     = (const float*)d_in[7];
    float*       out      = (float*)d_out;

    (void)in_sizes; (void)n_in; (void)out_size;

    gemm_kernel<<<(N_NODES + 15) / 16, 256>>>(x, W, att_src, att_dst);
    zero_count_kernel<<<NBLK_NODES, 256>>>();
    count_kernel<<<(N_EDGES + 255) / 256, 256>>>(ei);
    scanA_kernel<<<NBLK_NODES, 256>>>();
    scanB_kernel<<<1, 256>>>();
    scanC_kernel<<<NBLK_NODES, 256>>>();
    scatter_kernel<<<(N_EDGES + 255) / 256, 256>>>(ei);
    agg_kernel<<<(N_NODES * 32 + 255) / 256, 256>>>(bias, fc_w, fc_b, out);
}